// round 15
// baseline (speedup 1.0000x reference)
#include <cuda_runtime.h>
#include <cuda_fp16.h>
#include <math.h>
#include <stdint.h>

#define BB 8
#define NN 2048
#define DD 1024
typedef long long ll;
typedef __half fp16;

// ---------------- scratch (allocation-free rule: __device__ globals) ----------
__device__ fp16  g_uh[BB * NN * DD];       // normalized pairs
__device__ fp16  g_v16[BB * NN * DD];      // values, fp16 (n,d)
__device__ fp16  g_c[(ll)BB * NN * NN];    // coupling
__device__ fp16  g_sh[BB * NN * DD];       // S fp16
__device__ fp16  g_wh[DD * DD];            // W_in
__device__ fp16  g_wo[DD * DD];            // W_out

// ---------------- PTX helpers ------------------------------------------------
__device__ __forceinline__ uint32_t smem_u32(const void* p) {
    uint32_t a;
    asm("{ .reg .u64 t; cvta.to.shared.u64 t, %1; cvt.u32.u64 %0, t; }" : "=r"(a) : "l"(p));
    return a;
}
__device__ __forceinline__ void cpa16(uint32_t d, const void* s) {
    asm volatile("cp.async.cg.shared.global [%0], [%1], 16;" :: "r"(d), "l"(s));
}
__device__ __forceinline__ void cp_commit() { asm volatile("cp.async.commit_group;"); }
template <int N> __device__ __forceinline__ void cp_wait() {
    asm volatile("cp.async.wait_group %0;" :: "n"(N));
}
__device__ __forceinline__ void mma16(float* c, const uint32_t* a, const uint32_t* b) {
    asm volatile(
        "mma.sync.aligned.m16n8k16.row.col.f32.f16.f16.f32 "
        "{%0,%1,%2,%3}, {%4,%5,%6,%7}, {%8,%9}, {%0,%1,%2,%3};"
        : "+f"(c[0]), "+f"(c[1]), "+f"(c[2]), "+f"(c[3])
        : "r"(a[0]), "r"(a[1]), "r"(a[2]), "r"(a[3]), "r"(b[0]), "r"(b[1]));
}
__device__ __forceinline__ void ldsm4(uint32_t* r, uint32_t addr) {
    asm volatile("ldmatrix.sync.aligned.m8n8.x4.shared.b16 {%0,%1,%2,%3}, [%4];"
        : "=r"(r[0]), "=r"(r[1]), "=r"(r[2]), "=r"(r[3]) : "r"(addr));
}
__device__ __forceinline__ void ldsm4t(uint32_t* r, uint32_t addr) {
    asm volatile("ldmatrix.sync.aligned.m8n8.x4.trans.shared.b16 {%0,%1,%2,%3}, [%4];"
        : "=r"(r[0]), "=r"(r[1]), "=r"(r[2]), "=r"(r[3]) : "r"(addr));
}

// Block 128x128, 128 threads = 4 warps (2x2), warp tile 64x64. BK=64, 3 stages.
// K-major rows: 64 data + 8 pad fp16 = 144B (ldmatrix conflict-free).
// TRB (N-major) B tile: 64 k-rows x 128 n-cols, 272B stride (conflict-free).
#define ROWB 144
#define TILE_B (128 * ROWB)          // 18432 B
#define BROWB 272
#define BTILE_TR (64 * BROWB)        // 17408 B

// Fragment compute core shared by all kernels (A K-major; B K-major or TRB).
#define GEMM_CORE(As, Bs, TRBv)                                                  \
    _Pragma("unroll")                                                            \
    for (int ks = 0; ks < 4; ks++) {                                             \
        uint32_t af[4][4], bfr[8][2];                                            \
        _Pragma("unroll")                                                        \
        for (int i = 0; i < 4; i++)                                              \
            ldsm4(af[i], (As) + (uint32_t)(wm + i * 16) * ROWB + lmoff           \
                          + (uint32_t)ks * 32);                                  \
        _Pragma("unroll")                                                        \
        for (int jj = 0; jj < 4; jj++) {                                         \
            uint32_t t[4];                                                       \
            if (TRBv) {                                                          \
                ldsm4t(t, (Bs) + (uint32_t)ks * 16 * BROWB                       \
                             + (uint32_t)(wn + jj * 16) * 2 + lmoffB);           \
            } else {                                                             \
                ldsm4(t, (Bs) + (uint32_t)(wn + jj * 16) * ROWB + lmoff          \
                            + (uint32_t)ks * 32);                                \
            }                                                                    \
            bfr[2 * jj][0] = t[0]; bfr[2 * jj + 1][0] = TRBv ? t[2] : t[1];      \
            bfr[2 * jj][1] = TRBv ? t[1] : t[2]; bfr[2 * jj + 1][1] = t[3];      \
        }                                                                        \
        _Pragma("unroll")                                                        \
        for (int i = 0; i < 4; i++)                                              \
            _Pragma("unroll")                                                    \
            for (int j = 0; j < 8; j++)                                          \
                mma16(acc[i][j], af[i], bfr[j]);                                 \
    }

// ============ dual-output GEMM: uh = pairnorm(S@Win^T), v16 = g*(S@Wout^T) ====
__global__ __launch_bounds__(128) void hgemm_dual(
    const fp16* __restrict__ Ag, const fp16* __restrict__ B1,
    const fp16* __restrict__ B2, fp16* __restrict__ uOut,
    fp16* __restrict__ vOut, const float* __restrict__ G, int K, int ldC)
{
    extern __shared__ char dsm[];
    const int tid = threadIdx.x, lane = tid & 31, warp = tid >> 5;
    const int mq = lane >> 2, kq = lane & 3;
    const int wm = (warp >> 1) * 64, wn = (warp & 1) * 64;
    const int half = (int)(gridDim.x >> 1);
    const bool uPart = (int)blockIdx.x < half;
    const int colBlock = ((int)blockIdx.x % half) * 128;
    const int rowBlock = blockIdx.y * 128;

    const fp16* Ap = Ag + (ll)rowBlock * K;
    const fp16* Bp = (uPart ? B1 : B2) + (ll)colBlock * K;

    const uint32_t STAGE = 2u * TILE_B;
    uint32_t smem = smem_u32(dsm);

    const int sub = lane >> 3, l7 = lane & 7;
    const uint32_t lmoff  = (uint32_t)(((sub & 1) * 8 + l7) * ROWB  + (sub >> 1) * 16);
    const uint32_t lmoffB = 0; (void)lmoffB;

    float acc[4][8][4];
#pragma unroll
    for (int i = 0; i < 4; i++)
#pragma unroll
        for (int j = 0; j < 8; j++)
#pragma unroll
            for (int r = 0; r < 4; r++) acc[i][j][r] = 0.0f;

    auto load_K = [&](uint32_t ts, const fp16* g, int k0) {
#pragma unroll
        for (int h = 0; h < 8; h++) {
            int f = tid + h * 128;
            int r = f >> 3, c = f & 7;
            cpa16(ts + r * ROWB + c * 16, g + (ll)r * K + k0 + c * 8);
        }
    };
    auto prefetch = [&](int ch) {
        uint32_t bo = smem + (uint32_t)(ch % 3) * STAGE;
        int k0 = ch * 64;
        load_K(bo, Ap, k0);
        load_K(bo + TILE_B, Bp, k0);
        cp_commit();
    };

    const int CH = K >> 6;
    prefetch(0);
    prefetch(1);

    for (int ch = 0; ch < CH; ++ch) {
        cp_wait<1>();
        __syncthreads();
        if (ch + 2 < CH) prefetch(ch + 2); else cp_commit();
        uint32_t bo = smem + (uint32_t)(ch % 3) * STAGE;
        uint32_t As = bo, Bs = bo + TILE_B;
        GEMM_CORE(As, Bs, false)
    }

    // ---- epilogue ----
#pragma unroll
    for (int i = 0; i < 4; i++) {
        int r0 = rowBlock + wm + i * 16 + mq;
#pragma unroll
        for (int j = 0; j < 8; j++) {
            int c0 = colBlock + wn + j * 8 + 2 * kq;
#pragma unroll
            for (int h = 0; h < 2; h++) {
                int rr = r0 + h * 8;
                float x = acc[i][j][h * 2 + 0];
                float y = acc[i][j][h * 2 + 1];
                ll off = (ll)rr * ldC + c0;
                if (uPart) {
                    float xn = x + 1e-8f, yn = y + 1e-8f;
                    float inv = rsqrtf(xn * xn + yn * yn);
                    __half2 h2 = __floats2half2_rn(xn * inv, yn * inv);
                    *(uint32_t*)(uOut + off) = *(uint32_t*)&h2;
                } else {
                    float g = G[rr];
                    __half2 h2 = __floats2half2_rn(x * g, y * g);
                    *(uint32_t*)(vOut + off) = *(uint32_t*)&h2;
                }
            }
        }
    }
}

// ============ GEMM6: field = coupling @ values (B N-major via ldmatrix.trans) =
__global__ __launch_bounds__(128) void hgemm_tr(
    const fp16* __restrict__ Ag, const fp16* __restrict__ Bg,
    float* __restrict__ Cg, int K, int ldC, int ldB,
    ll sA, ll sB, ll sC)
{
    extern __shared__ char dsm[];
    const int tid = threadIdx.x, lane = tid & 31, warp = tid >> 5;
    const int mq = lane >> 2, kq = lane & 3;
    const int wm = (warp >> 1) * 64, wn = (warp & 1) * 64;
    const int b = blockIdx.z;
    const int rowBlock = blockIdx.y * 128, colBlock = blockIdx.x * 128;

    const fp16* Ap = Ag + (ll)b * sA + (ll)rowBlock * K;
    const fp16* Bp = Bg + (ll)b * sB + colBlock;
    float* C = Cg + (ll)b * sC;

    const uint32_t STAGE = TILE_B + BTILE_TR;
    uint32_t smem = smem_u32(dsm);

    const int sub = lane >> 3, l7 = lane & 7;
    const uint32_t lmoff  = (uint32_t)(((sub & 1) * 8 + l7) * ROWB  + (sub >> 1) * 16);
    const uint32_t lmoffB = (uint32_t)(((sub & 1) * 8 + l7) * BROWB + (sub >> 1) * 16);

    float acc[4][8][4];
#pragma unroll
    for (int i = 0; i < 4; i++)
#pragma unroll
        for (int j = 0; j < 8; j++)
#pragma unroll
            for (int r = 0; r < 4; r++) acc[i][j][r] = 0.0f;

    auto prefetch = [&](int ch) {
        uint32_t bo = smem + (uint32_t)(ch % 3) * STAGE;
        int k0 = ch * 64;
#pragma unroll
        for (int h = 0; h < 8; h++) {
            int f = tid + h * 128;
            int r = f >> 3, c = f & 7;
            cpa16(bo + r * ROWB + c * 16, Ap + (ll)r * K + k0 + c * 8);
        }
#pragma unroll
        for (int h = 0; h < 8; h++) {
            int f = tid + h * 128;
            int r = f >> 4, c = f & 15;
            cpa16(bo + TILE_B + r * BROWB + c * 16, Bp + (ll)(k0 + r) * ldB + c * 8);
        }
        cp_commit();
    };

    const int CH = K >> 6;
    prefetch(0);
    prefetch(1);

    for (int ch = 0; ch < CH; ++ch) {
        cp_wait<1>();
        __syncthreads();
        if (ch + 2 < CH) prefetch(ch + 2); else cp_commit();
        uint32_t bo = smem + (uint32_t)(ch % 3) * STAGE;
        uint32_t As = bo, Bs = bo + TILE_B;
        GEMM_CORE(As, Bs, true)
    }

#pragma unroll
    for (int i = 0; i < 4; i++) {
        int r0 = rowBlock + wm + i * 16 + mq;
#pragma unroll
        for (int j = 0; j < 8; j++) {
            int c0 = colBlock + wn + j * 8 + 2 * kq;
#pragma unroll
            for (int h = 0; h < 2; h++) {
                int rr = r0 + h * 8;
                ll off = (ll)rr * ldC + c0;
                *(float2*)(C + off) =
                    make_float2(acc[i][j][h * 2 + 0], acc[i][j][h * 2 + 1]);
            }
        }
    }
}

// ============ symmetric resonance GEMM (upper-tri tiles, mirror epilogue) ====
__global__ __launch_bounds__(128) void hgemm_sym(
    const fp16* __restrict__ Ag, float* __restrict__ Cg, int K, int ldC,
    ll sA, ll sC, const float* __restrict__ raccIn, float resScale)
{
    extern __shared__ char dsm[];
    const int tid = threadIdx.x, lane = tid & 31, warp = tid >> 5;
    const int mq = lane >> 2, kq = lane & 3;
    const int wm = (warp >> 1) * 64, wn = (warp & 1) * 64;
    const int b = blockIdx.z;

    int T = ldC >> 7;
    int t = blockIdx.x, bi = 0;
    while (t >= T - bi) { t -= T - bi; bi++; }
    const int rowBlock = bi * 128;
    const int colBlock = (bi + t) * 128;

    const fp16* Ap = Ag + (ll)b * sA + (ll)rowBlock * K;
    const fp16* Bp = Ag + (ll)b * sA + (ll)colBlock * K;
    float* C = Cg + (ll)b * sC;

    const uint32_t STAGE = 2u * TILE_B;
    uint32_t smem = smem_u32(dsm);

    const int sub = lane >> 3, l7 = lane & 7;
    const uint32_t lmoff  = (uint32_t)(((sub & 1) * 8 + l7) * ROWB + (sub >> 1) * 16);
    const uint32_t lmoffB = 0; (void)lmoffB;

    float acc[4][8][4];
#pragma unroll
    for (int i = 0; i < 4; i++)
#pragma unroll
        for (int j = 0; j < 8; j++)
#pragma unroll
            for (int r = 0; r < 4; r++) acc[i][j][r] = 0.0f;

    auto load_K = [&](uint32_t ts, const fp16* g, int k0) {
#pragma unroll
        for (int h = 0; h < 8; h++) {
            int f = tid + h * 128;
            int r = f >> 3, c = f & 7;
            cpa16(ts + r * ROWB + c * 16, g + (ll)r * K + k0 + c * 8);
        }
    };
    auto prefetch = [&](int ch) {
        uint32_t bo = smem + (uint32_t)(ch % 3) * STAGE;
        int k0 = ch * 64;
        load_K(bo, Ap, k0);
        load_K(bo + TILE_B, Bp, k0);
        cp_commit();
    };

    const int CH = K >> 6;
    prefetch(0);
    prefetch(1);

    for (int ch = 0; ch < CH; ++ch) {
        cp_wait<1>();
        __syncthreads();
        if (ch + 2 < CH) prefetch(ch + 2); else cp_commit();
        uint32_t bo = smem + (uint32_t)(ch % 3) * STAGE;
        uint32_t As = bo, Bs = bo + TILE_B;
        GEMM_CORE(As, Bs, false)
    }

    const float* raccB = raccIn + (ll)b * sC;
    const bool mirror = (rowBlock != colBlock);
#pragma unroll
    for (int i = 0; i < 4; i++) {
        int r0 = rowBlock + wm + i * 16 + mq;
#pragma unroll
        for (int j = 0; j < 8; j++) {
            int c0 = colBlock + wn + j * 8 + 2 * kq;
#pragma unroll
            for (int h = 0; h < 2; h++) {
                int rr = r0 + h * 8;
                float x = acc[i][j][h * 2 + 0];
                float y = acc[i][j][h * 2 + 1];
                ll off = (ll)rr * ldC + c0;
                float2 rv = *(const float2*)(raccB + off);
                float ox = fminf(fmaxf(0.7f * rv.x + resScale * x, -2.0f), 2.0f);
                float oy = fminf(fmaxf(0.7f * rv.y + resScale * y, -2.0f), 2.0f);
                *(float2*)(C + off) = make_float2(ox, oy);
                if (mirror) {
                    ll t0 = (ll)c0 * ldC + rr;
                    ll t1 = t0 + ldC;
                    float rx = raccB[t0], ry = raccB[t1];
                    C[t0] = fminf(fmaxf(0.7f * rx + resScale * x, -2.0f), 2.0f);
                    C[t1] = fminf(fmaxf(0.7f * ry + resScale * y, -2.0f), 2.0f);
                }
            }
        }
    }
}

// ---------------- elementwise kernels ----------------------------------------
__global__ void conv_s_kernel(const float* __restrict__ S, fp16* __restrict__ Sh) {
    ll i = (ll)blockIdx.x * blockDim.x + threadIdx.x;
    if (i >= (ll)BB * NN * DD) return;
    Sh[i] = __float2half_rn(S[i]);
}

__global__ void conv_w_kernel(const float* __restrict__ Win, const float* __restrict__ Wout,
                              fp16* __restrict__ Wh, fp16* __restrict__ Wo) {
    int i = blockIdx.x * blockDim.x + threadIdx.x;
    if (i >= DD * DD) return;
    Wh[i] = __float2half_rn(Win[i]);
    Wo[i] = __float2half_rn(Wout[i]);
}

// per (b,n) row: sigmoid, gates, zero diag, row-normalize -> fp16
__global__ __launch_bounds__(256) void coupling_kernel(
    const float* __restrict__ raccNew, const float* __restrict__ gates,
    const float* __restrict__ condPtr, fp16* __restrict__ cOut)
{
    int n = blockIdx.x, b = blockIdx.y;
    const float* row = raccNew + ((ll)b * NN + n) * NN;
    ll obase = ((ll)b * NN + n) * NN;
    float cond = fminf(fmaxf(condPtr[0], -5.0f), 5.0f);
    float gn = gates[b * NN + n];
    int t = threadIdx.x;
    float local[NN / 256];
    float sum = 0.0f;
#pragma unroll
    for (int it = 0; it < NN / 256; it++) {
        int m = t + it * 256;
        float s = 1.0f / (1.0f + expf(-cond * row[m]));
        float c = s * gates[b * NN + m] * gn;
        if (m == n) c = 0.0f;
        local[it] = c;
        sum += c;
    }
    __shared__ float red[256];
    red[t] = sum;
    __syncthreads();
    for (int s = 128; s > 0; s >>= 1) {
        if (t < s) red[t] += red[t + s];
        __syncthreads();
    }
    float inv = 1.0f / (red[0] + 1e-8f);
#pragma unroll
    for (int it = 0; it < NN / 256; it++)
        cOut[obase + t + it * 256] = __float2half_rn(local[it] * inv);
}

// ---------------- launch -----------------------------------------------------
extern "C" void kernel_launch(void* const* d_in, const int* in_sizes, int n_in,
                              void* d_out, int out_size) {
    const float* S    = (const float*)d_in[0];
    const float* G    = (const float*)d_in[1];
    const float* Racc = (const float*)d_in[2];
    const float* Win  = (const float*)d_in[3];
    const float* Wout = (const float*)d_in[4];
    const float* cond = (const float*)d_in[5];

    float* field = (float*)d_out;                 // (B,N,D)
    float* raccO = field + (size_t)BB * NN * DD;  // (B,N,N)

    fp16 *uh, *v16, *c16, *sh, *wh, *wo;
    cudaGetSymbolAddress((void**)&uh, g_uh);
    cudaGetSymbolAddress((void**)&v16, g_v16);
    cudaGetSymbolAddress((void**)&c16, g_c);
    cudaGetSymbolAddress((void**)&sh, g_sh);
    cudaGetSymbolAddress((void**)&wh, g_wh);
    cudaGetSymbolAddress((void**)&wo, g_wo);

    const int SM_KK = 3 * 2 * TILE_B;               // 110592
    const int SM_TR = 3 * (TILE_B + BTILE_TR);      // 107520
    cudaFuncSetAttribute(hgemm_dual, cudaFuncAttributeMaxDynamicSharedMemorySize, SM_KK);
    cudaFuncSetAttribute(hgemm_tr,   cudaFuncAttributeMaxDynamicSharedMemorySize, SM_TR);
    cudaFuncSetAttribute(hgemm_sym,  cudaFuncAttributeMaxDynamicSharedMemorySize, SM_KK);
    cudaFuncSetAttribute(hgemm_dual, cudaFuncAttributePreferredSharedMemoryCarveout, 100);
    cudaFuncSetAttribute(hgemm_tr,   cudaFuncAttributePreferredSharedMemoryCarveout, 100);
    cudaFuncSetAttribute(hgemm_sym,  cudaFuncAttributePreferredSharedMemoryCarveout, 100);

    const ll M1 = (ll)BB * NN;  // 16384

    // 0. conversions
    conv_s_kernel<<<(int)((M1 * DD + 255) / 256), 256>>>(S, sh);
    conv_w_kernel<<<(DD * DD + 255) / 256, 256>>>(Win, Wout, wh, wo);

    // 1+2+5 fused: uh = pairnorm(S@Win^T); v16 = g * (S@Wout^T)
    hgemm_dual<<<dim3(16, (int)(M1 / 128), 1), 128, SM_KK>>>(
        sh, wh, wo, uh, v16, G, DD, DD);

    // 3. raccO = clip(0.7*racc + (0.3/pairs) * U U^T, -2, 2)  (symmetric tiles)
    hgemm_sym<<<dim3(136, 1, BB), 128, SM_KK>>>(
        uh, raccO, DD, NN, (ll)NN * DD, (ll)NN * NN, Racc, 0.3f / (float)(DD / 2));

    // 4. coupling rows -> fp16
    coupling_kernel<<<dim3(NN, BB), 256>>>(raccO, G, cond, c16);

    // 6. field = coupling @ values
    hgemm_tr<<<dim3(DD / 128, NN / 128, BB), 128, SM_TR>>>(
        c16, v16, field, NN, DD, DD,
        (ll)NN * NN, (ll)NN * DD, (ll)NN * DD);
}

// round 16
// speedup vs baseline: 1.0934x; 1.0934x over previous
#include <cuda_runtime.h>
#include <cuda_fp16.h>
#include <math.h>
#include <stdint.h>

#define BB 8
#define NN 2048
#define DD 1024
typedef long long ll;
typedef __half fp16;

// ---------------- scratch (allocation-free rule: __device__ globals) ----------
__device__ fp16  g_uh[BB * NN * DD];       // normalized pairs (GEMM1 fused out)
__device__ fp16  g_v16[BB * NN * DD];      // values, fp16 (n,d) natural layout
__device__ fp16  g_c[(ll)BB * NN * NN];    // coupling
__device__ fp16  g_sh[BB * NN * DD];       // S (ungated)
__device__ fp16  g_sg[BB * NN * DD];       // S*g
__device__ fp16  g_wh[DD * DD];            // W_in
__device__ fp16  g_wo[DD * DD];            // W_out

// ---------------- PTX helpers ------------------------------------------------
__device__ __forceinline__ uint32_t smem_u32(const void* p) {
    uint32_t a;
    asm("{ .reg .u64 t; cvta.to.shared.u64 t, %1; cvt.u32.u64 %0, t; }" : "=r"(a) : "l"(p));
    return a;
}
__device__ __forceinline__ void cpa16(uint32_t d, const void* s) {
    asm volatile("cp.async.cg.shared.global [%0], [%1], 16;" :: "r"(d), "l"(s));
}
__device__ __forceinline__ void cp_commit() { asm volatile("cp.async.commit_group;"); }
template <int N> __device__ __forceinline__ void cp_wait() {
    asm volatile("cp.async.wait_group %0;" :: "n"(N));
}
__device__ __forceinline__ void mma16(float* c, const uint32_t* a, const uint32_t* b) {
    asm volatile(
        "mma.sync.aligned.m16n8k16.row.col.f32.f16.f16.f32 "
        "{%0,%1,%2,%3}, {%4,%5,%6,%7}, {%8,%9}, {%0,%1,%2,%3};"
        : "+f"(c[0]), "+f"(c[1]), "+f"(c[2]), "+f"(c[3])
        : "r"(a[0]), "r"(a[1]), "r"(a[2]), "r"(a[3]), "r"(b[0]), "r"(b[1]));
}
__device__ __forceinline__ void ldsm4(uint32_t* r, uint32_t addr) {
    asm volatile("ldmatrix.sync.aligned.m8n8.x4.shared.b16 {%0,%1,%2,%3}, [%4];"
        : "=r"(r[0]), "=r"(r[1]), "=r"(r[2]), "=r"(r[3]) : "r"(addr));
}
__device__ __forceinline__ void ldsm4t(uint32_t* r, uint32_t addr) {
    asm volatile("ldmatrix.sync.aligned.m8n8.x4.trans.shared.b16 {%0,%1,%2,%3}, [%4];"
        : "=r"(r[0]), "=r"(r[1]), "=r"(r[2]), "=r"(r[3]) : "r"(addr));
}

// Tile geometry: 128x128 block, BK=64, 8 warps (2x4), warp tile 64x32. 3 stages.
// K-major smem rows: 64 data + 8 pad fp16 = 144B stride (conflict-free ldmatrix).
// TRB (N-major) B tile: 64 k-rows x 128 n-cols, 272B stride (conflict-free).
#define ROWB 144
#define TILE_B (128 * ROWB)          // 18432 B, 128x64 K-major tile
#define BROWB 272
#define BTILE_TR (64 * BROWB)        // 17408 B, 64x128 N-major tile

// EPI: 0 = f32 store; 3 = fused pairnorm -> fp16 pairs; 4 = fp16 store.
// TRB: B given as [Ktot, ldB] row-major (N-major tile + ldmatrix.trans).
template <int EPI, bool TRB>
__global__ __launch_bounds__(256) void hgemm(
    const fp16* __restrict__ Ag, const fp16* __restrict__ Bg,
    float* __restrict__ Cg, int K, int ldC, int ldB,
    ll sA, ll sB, ll sC)
{
    extern __shared__ char dsm[];
    const int tid = threadIdx.x, lane = tid & 31, warp = tid >> 5;
    const int mq = lane >> 2, kq = lane & 3;
    const int wm = (warp >> 2) * 64, wn = (warp & 3) * 32;
    const int b = blockIdx.z;
    const int rowBlock = blockIdx.y * 128, colBlock = blockIdx.x * 128;

    const fp16* Ap = Ag + (ll)b * sA + (ll)rowBlock * K;
    const fp16* Bp = TRB ? (Bg + (ll)b * sB + colBlock)
                         : (Bg + (ll)b * sB + (ll)colBlock * K);
    float* C = Cg + (ll)b * sC;

    const uint32_t STAGE = TILE_B + (TRB ? BTILE_TR : TILE_B);
    uint32_t smem = smem_u32(dsm);

    const int sub = lane >> 3, l7 = lane & 7;
    const uint32_t lmoff  = (uint32_t)(((sub & 1) * 8 + l7) * ROWB  + (sub >> 1) * 16);
    const uint32_t lmoffB = (uint32_t)(((sub & 1) * 8 + l7) * BROWB + (sub >> 1) * 16);

    float acc[4][4][4];
#pragma unroll
    for (int i = 0; i < 4; i++)
#pragma unroll
        for (int j = 0; j < 4; j++)
#pragma unroll
            for (int r = 0; r < 4; r++) acc[i][j][r] = 0.0f;

    auto load_A = [&](uint32_t ts, int k0) {
#pragma unroll
        for (int h = 0; h < 4; h++) {
            int f = tid + h * 256;
            int r = f >> 3, c = f & 7;
            cpa16(ts + r * ROWB + c * 16, Ap + (ll)r * K + k0 + c * 8);
        }
    };
    auto load_B = [&](uint32_t ts, int k0) {
        if (TRB) {
#pragma unroll
            for (int h = 0; h < 4; h++) {
                int f = tid + h * 256;
                int r = f >> 4, c = f & 15;   // r: k-row 0..63, c: 16B n-chunk
                cpa16(ts + r * BROWB + c * 16, Bp + (ll)(k0 + r) * ldB + c * 8);
            }
        } else {
#pragma unroll
            for (int h = 0; h < 4; h++) {
                int f = tid + h * 256;
                int r = f >> 3, c = f & 7;
                cpa16(ts + r * ROWB + c * 16, Bp + (ll)r * K + k0 + c * 8);
            }
        }
    };
    auto prefetch = [&](int ch) {
        uint32_t bo = smem + (uint32_t)(ch % 3) * STAGE;
        int k0 = ch * 64;
        load_A(bo, k0);
        load_B(bo + TILE_B, k0);
        cp_commit();
    };

    const int CH = K >> 6;
    prefetch(0);
    prefetch(1);

    for (int ch = 0; ch < CH; ++ch) {
        cp_wait<1>();                     // stage ch complete (this warp)
        __syncthreads();                  // all warps done with stage ch-1
        if (ch + 2 < CH) prefetch(ch + 2);
        else             cp_commit();     // empty group keeps counts aligned

        uint32_t bo = smem + (uint32_t)(ch % 3) * STAGE;
        uint32_t As = bo, Bs = bo + TILE_B;

#pragma unroll
        for (int ks = 0; ks < 4; ks++) {
            uint32_t af[4][4], bfr[4][2];
#pragma unroll
            for (int i = 0; i < 4; i++)
                ldsm4(af[i], As + (uint32_t)(wm + i * 16) * ROWB + lmoff
                              + (uint32_t)ks * 32);
#pragma unroll
            for (int jj = 0; jj < 2; jj++) {
                uint32_t t[4];
                if (TRB) {
                    ldsm4t(t, Bs + (uint32_t)ks * 16 * BROWB
                                 + (uint32_t)(wn + jj * 16) * 2 + lmoffB);
                } else {
                    ldsm4(t, Bs + (uint32_t)(wn + jj * 16) * ROWB + lmoff
                                + (uint32_t)ks * 32);
                }
                bfr[2 * jj][0] = t[0]; bfr[2 * jj + 1][0] = TRB ? t[2] : t[1];
                bfr[2 * jj][1] = TRB ? t[1] : t[2]; bfr[2 * jj + 1][1] = t[3];
            }
#pragma unroll
            for (int i = 0; i < 4; i++)
#pragma unroll
                for (int j = 0; j < 4; j++)
                    mma16(acc[i][j], af[i], bfr[j]);
        }
    }

    // ---- epilogue ----
#pragma unroll
    for (int i = 0; i < 4; i++) {
        int r0 = rowBlock + wm + i * 16 + mq;
#pragma unroll
        for (int j = 0; j < 4; j++) {
            int c0 = colBlock + wn + j * 8 + 2 * kq;
#pragma unroll
            for (int h = 0; h < 2; h++) {
                int rr = r0 + h * 8;
                float x = acc[i][j][h * 2 + 0];
                float y = acc[i][j][h * 2 + 1];
                ll off = (ll)rr * ldC + c0;
                if (EPI == 3) {
                    float xn = x + 1e-8f, yn = y + 1e-8f;
                    float inv = rsqrtf(xn * xn + yn * yn);
                    __half2 h2 = __floats2half2_rn(xn * inv, yn * inv);
                    *(uint32_t*)((fp16*)Cg + (ll)b * sC + off) = *(uint32_t*)&h2;
                } else if (EPI == 4) {
                    __half2 h2 = __floats2half2_rn(x, y);
                    *(uint32_t*)((fp16*)Cg + (ll)b * sC + off) = *(uint32_t*)&h2;
                } else {
                    *(float2*)(C + off) = make_float2(x, y);
                }
            }
        }
    }
}

// ============ symmetric resonance GEMM (upper-tri tiles, mirror epilogue) ====
__global__ __launch_bounds__(256) void hgemm_sym(
    const fp16* __restrict__ Ag, float* __restrict__ Cg, int K, int ldC,
    ll sA, ll sC, const float* __restrict__ raccIn, float resScale)
{
    extern __shared__ char dsm[];
    const int tid = threadIdx.x, lane = tid & 31, warp = tid >> 5;
    const int mq = lane >> 2, kq = lane & 3;
    const int wm = (warp >> 2) * 64, wn = (warp & 3) * 32;
    const int b = blockIdx.z;

    int T = ldC >> 7;
    int t = blockIdx.x, bi = 0;
    while (t >= T - bi) { t -= T - bi; bi++; }
    const int rowBlock = bi * 128;
    const int colBlock = (bi + t) * 128;

    const fp16* Ap = Ag + (ll)b * sA + (ll)rowBlock * K;
    const fp16* Bp = Ag + (ll)b * sA + (ll)colBlock * K;
    float* C = Cg + (ll)b * sC;

    const uint32_t STAGE = 2u * TILE_B;
    uint32_t smem = smem_u32(dsm);

    const int sub = lane >> 3, l7 = lane & 7;
    const uint32_t lmoff = (uint32_t)(((sub & 1) * 8 + l7) * ROWB + (sub >> 1) * 16);

    float acc[4][4][4];
#pragma unroll
    for (int i = 0; i < 4; i++)
#pragma unroll
        for (int j = 0; j < 4; j++)
#pragma unroll
            for (int r = 0; r < 4; r++) acc[i][j][r] = 0.0f;

    auto load_tile = [&](uint32_t ts, const fp16* g, int k0) {
#pragma unroll
        for (int h = 0; h < 4; h++) {
            int f = tid + h * 256;
            int r = f >> 3, c = f & 7;
            cpa16(ts + r * ROWB + c * 16, g + (ll)r * K + k0 + c * 8);
        }
    };
    auto prefetch = [&](int ch) {
        uint32_t bo = smem + (uint32_t)(ch % 3) * STAGE;
        int k0 = ch * 64;
        load_tile(bo, Ap, k0);
        load_tile(bo + TILE_B, Bp, k0);
        cp_commit();
    };

    const int CH = K >> 6;
    prefetch(0);
    prefetch(1);

    for (int ch = 0; ch < CH; ++ch) {
        cp_wait<1>();
        __syncthreads();
        if (ch + 2 < CH) prefetch(ch + 2);
        else             cp_commit();

        uint32_t bo = smem + (uint32_t)(ch % 3) * STAGE;
        uint32_t As = bo, Bs = bo + TILE_B;

#pragma unroll
        for (int ks = 0; ks < 4; ks++) {
            const uint32_t ko = (uint32_t)ks * 32;
            uint32_t af[4][4], bfr[4][2];
#pragma unroll
            for (int i = 0; i < 4; i++)
                ldsm4(af[i], As + (uint32_t)(wm + i * 16) * ROWB + lmoff + ko);
#pragma unroll
            for (int jj = 0; jj < 2; jj++) {
                uint32_t t4[4];
                ldsm4(t4, Bs + (uint32_t)(wn + jj * 16) * ROWB + lmoff + ko);
                bfr[2 * jj][0] = t4[0]; bfr[2 * jj + 1][0] = t4[1];
                bfr[2 * jj][1] = t4[2]; bfr[2 * jj + 1][1] = t4[3];
            }
#pragma unroll
            for (int i = 0; i < 4; i++)
#pragma unroll
                for (int j = 0; j < 4; j++)
                    mma16(acc[i][j], af[i], bfr[j]);
        }
    }

    const float* raccB = raccIn + (ll)b * sC;
    const bool mirror = (rowBlock != colBlock);
#pragma unroll
    for (int i = 0; i < 4; i++) {
        int r0 = rowBlock + wm + i * 16 + mq;
#pragma unroll
        for (int j = 0; j < 4; j++) {
            int c0 = colBlock + wn + j * 8 + 2 * kq;
#pragma unroll
            for (int h = 0; h < 2; h++) {
                int rr = r0 + h * 8;
                float x = acc[i][j][h * 2 + 0];
                float y = acc[i][j][h * 2 + 1];
                ll off = (ll)rr * ldC + c0;
                float2 rv = *(const float2*)(raccB + off);
                float ox = fminf(fmaxf(0.7f * rv.x + resScale * x, -2.0f), 2.0f);
                float oy = fminf(fmaxf(0.7f * rv.y + resScale * y, -2.0f), 2.0f);
                *(float2*)(C + off) = make_float2(ox, oy);
                if (mirror) {
                    ll t0 = (ll)c0 * ldC + rr;
                    ll t1 = t0 + ldC;
                    float rx = raccB[t0], ry = raccB[t1];
                    C[t0] = fminf(fmaxf(0.7f * rx + resScale * x, -2.0f), 2.0f);
                    C[t1] = fminf(fmaxf(0.7f * ry + resScale * y, -2.0f), 2.0f);
                }
            }
        }
    }
}

// ---------------- elementwise kernels ----------------------------------------
__global__ void conv_s_kernel(const float* __restrict__ S, const float* __restrict__ G,
                              fp16* __restrict__ Sh, fp16* __restrict__ SG) {
    ll i = (ll)blockIdx.x * blockDim.x + threadIdx.x;
    if (i >= (ll)BB * NN * DD) return;
    float s = S[i];
    Sh[i] = __float2half_rn(s);
    SG[i] = __float2half_rn(s * G[i >> 10]);
}

__global__ void conv_w_kernel(const float* __restrict__ Win, const float* __restrict__ Wout,
                              fp16* __restrict__ Wh, fp16* __restrict__ Wo) {
    int i = blockIdx.x * blockDim.x + threadIdx.x;
    if (i >= DD * DD) return;
    Wh[i] = __float2half_rn(Win[i]);
    Wo[i] = __float2half_rn(Wout[i]);
}

// per (b,n) row: sigmoid, gates, zero diag, row-normalize -> fp16.
// float4-vectorized: 256 threads x 2 float4 = 2048 elements per row.
__global__ __launch_bounds__(256) void coupling_kernel(
    const float* __restrict__ raccNew, const float* __restrict__ gates,
    const float* __restrict__ condPtr, fp16* __restrict__ cOut)
{
    int n = blockIdx.x, b = blockIdx.y;
    const float4* row = (const float4*)(raccNew + ((ll)b * NN + n) * NN);
    const float4* g4  = (const float4*)(gates + (ll)b * NN);
    fp16* out = cOut + ((ll)b * NN + n) * NN;
    float cond = fminf(fmaxf(condPtr[0], -5.0f), 5.0f);
    float gn = gates[b * NN + n];
    int t = threadIdx.x, lane = t & 31, warp = t >> 5;

    float vals[2][4];
    float lsum = 0.0f;
#pragma unroll
    for (int it = 0; it < 2; it++) {
        int m4 = t + it * 256;          // float4 index (0..511)
        float4 v = row[m4];
        float4 g = g4[m4];
        float c0 = gn * g.x / (1.0f + expf(-cond * v.x));
        float c1 = gn * g.y / (1.0f + expf(-cond * v.y));
        float c2 = gn * g.z / (1.0f + expf(-cond * v.z));
        float c3 = gn * g.w / (1.0f + expf(-cond * v.w));
        int mb = m4 * 4;
        if (mb + 0 == n) c0 = 0.0f;
        if (mb + 1 == n) c1 = 0.0f;
        if (mb + 2 == n) c2 = 0.0f;
        if (mb + 3 == n) c3 = 0.0f;
        vals[it][0] = c0; vals[it][1] = c1; vals[it][2] = c2; vals[it][3] = c3;
        lsum += (c0 + c1) + (c2 + c3);
    }
#pragma unroll
    for (int o = 16; o > 0; o >>= 1) lsum += __shfl_xor_sync(0xffffffffu, lsum, o);
    __shared__ float ws[8];
    if (lane == 0) ws[warp] = lsum;
    __syncthreads();
    float tot = 0.0f;
#pragma unroll
    for (int i = 0; i < 8; i++) tot += ws[i];
    float inv = 1.0f / (tot + 1e-8f);

#pragma unroll
    for (int it = 0; it < 2; it++) {
        int m4 = t + it * 256;
        __half2 lo = __floats2half2_rn(vals[it][0] * inv, vals[it][1] * inv);
        __half2 hi = __floats2half2_rn(vals[it][2] * inv, vals[it][3] * inv);
        uint2 pk;
        pk.x = *(uint32_t*)&lo;
        pk.y = *(uint32_t*)&hi;
        *(uint2*)(out + m4 * 4) = pk;
    }
}

// ---------------- launch -----------------------------------------------------
extern "C" void kernel_launch(void* const* d_in, const int* in_sizes, int n_in,
                              void* d_out, int out_size) {
    const float* S    = (const float*)d_in[0];
    const float* G    = (const float*)d_in[1];
    const float* Racc = (const float*)d_in[2];
    const float* Win  = (const float*)d_in[3];
    const float* Wout = (const float*)d_in[4];
    const float* cond = (const float*)d_in[5];

    float* field = (float*)d_out;                 // (B,N,D)
    float* raccO = field + (size_t)BB * NN * DD;  // (B,N,N)

    fp16 *uh, *v16, *c16, *sh, *sg, *wh, *wo;
    cudaGetSymbolAddress((void**)&uh, g_uh);
    cudaGetSymbolAddress((void**)&v16, g_v16);
    cudaGetSymbolAddress((void**)&c16, g_c);
    cudaGetSymbolAddress((void**)&sh, g_sh);
    cudaGetSymbolAddress((void**)&sg, g_sg);
    cudaGetSymbolAddress((void**)&wh, g_wh);
    cudaGetSymbolAddress((void**)&wo, g_wo);

    const int SM_KK = 3 * 2 * TILE_B;               // 110592
    const int SM_TR = 3 * (TILE_B + BTILE_TR);      // 107520
    cudaFuncSetAttribute(hgemm<3, false>, cudaFuncAttributeMaxDynamicSharedMemorySize, SM_KK);
    cudaFuncSetAttribute(hgemm<4, false>, cudaFuncAttributeMaxDynamicSharedMemorySize, SM_KK);
    cudaFuncSetAttribute(hgemm<0, true>,  cudaFuncAttributeMaxDynamicSharedMemorySize, SM_TR);
    cudaFuncSetAttribute(hgemm_sym, cudaFuncAttributeMaxDynamicSharedMemorySize, SM_KK);
    cudaFuncSetAttribute(hgemm<3, false>, cudaFuncAttributePreferredSharedMemoryCarveout, 100);
    cudaFuncSetAttribute(hgemm<4, false>, cudaFuncAttributePreferredSharedMemoryCarveout, 100);
    cudaFuncSetAttribute(hgemm<0, true>,  cudaFuncAttributePreferredSharedMemoryCarveout, 100);
    cudaFuncSetAttribute(hgemm_sym, cudaFuncAttributePreferredSharedMemoryCarveout, 100);

    const ll M1 = (ll)BB * NN;  // 16384

    // 0. conversions
    conv_s_kernel<<<(int)((M1 * DD + 255) / 256), 256>>>(S, G, sh, sg);
    conv_w_kernel<<<(DD * DD + 255) / 256, 256>>>(Win, Wout, wh, wo);

    // 1+2. uh = pairnorm(S @ Win^T) fused
    hgemm<3, false><<<dim3(DD / 128, (int)(M1 / 128), 1), 256, SM_KK>>>(
        sh, wh, (float*)uh, DD, DD, DD, 0, 0, 0);

    // 3. raccO = clip(0.7*racc + (0.3/pairs) * U U^T, -2, 2)  (symmetric tiles)
    hgemm_sym<<<dim3(136, 1, BB), 256, SM_KK>>>(
        uh, raccO, DD, NN, (ll)NN * DD, (ll)NN * NN, Racc, 0.3f / (float)(DD / 2));

    // 4. coupling rows -> fp16 (vectorized)
    coupling_kernel<<<dim3(NN, BB), 256>>>(raccO, G, cond, c16);

    // 5. v16 = (S*g) @ Wout^T   (fp16 out, natural (n,d) layout)
    hgemm<4, false><<<dim3(DD / 128, (int)(M1 / 128), 1), 256, SM_KK>>>(
        sg, wo, (float*)v16, DD, DD, DD, 0, 0, 0);

    // 6. field = coupling @ values   (B consumed N-major via ldmatrix.trans)
    hgemm<0, true><<<dim3(DD / 128, NN / 128, BB), 256, SM_TR>>>(
        c16, v16, field, NN, DD, DD,
        (ll)NN * NN, (ll)NN * DD, (ll)NN * DD);
}